// round 11
// baseline (speedup 1.0000x reference)
#include <cuda_runtime.h>
#include <cuda_bf16.h>
#include <math.h>

// Problem constants (fixed by dataset: B=4, H=W=320)
#define H_DIM 320
#define W_DIM 320
#define B_DIM 4
#define TILE 32                 // tile is 32x32 pixels
#define HALO 8
#define SROWS (TILE + 2 * HALO) // 48 mask rows
#define NBLK_X (W_DIM / TILE)   // 10
#define NBLK_Y (H_DIM / TILE)   // 10
#define NBLOCKS (NBLK_X * NBLK_Y * B_DIM) // 400
#define FP_SCALE 16777216.0     // 2^24 fixed-point scale (associative int adds)

__device__ unsigned long long g_sum = 0ull;
__device__ unsigned int g_arrived = 0;

// Exact global fallback (entered with INF bound; window results <= 81 are
// provably the exact global min since outside-window seeds have d^2 >= 81).
__device__ __noinline__ int global_ring_search(const int* __restrict__ targets,
                                               int planeOff, int gh, int gw, int best)
{
    for (int r = HALO + 1; r < H_DIM + W_DIM; ++r) {
        if (r * r >= best) break;
        const int rr = r * r;
        const int yT = gh - r, yB = gh + r;
        for (int dx = -r; dx <= r; ++dx) {
            int d2 = rr + dx * dx;
            if (d2 >= best) continue;
            int x = gw + dx;
            if (x < 0 || x >= W_DIM) continue;
            if (yT >= 0 && targets[planeOff + yT * W_DIM + x] > 0) best = d2;
            if (yB < H_DIM && d2 < best && targets[planeOff + yB * W_DIM + x] > 0) best = d2;
        }
        const int xL = gw - r, xR = gw + r;
        for (int dy = -r + 1; dy <= r - 1; ++dy) {
            int d2 = rr + dy * dy;
            if (d2 >= best) continue;
            int y = gh + dy;
            if (y < 0 || y >= H_DIM) continue;
            if (xL >= 0 && targets[planeOff + y * W_DIM + xL] > 0) best = d2;
            if (xR < W_DIM && d2 < best && targets[planeOff + y * W_DIM + xR] > 0) best = d2;
        }
    }
    return best;
}

__global__ __launch_bounds__(256)
void edt_loss_kernel(const float* __restrict__ logits,
                     const int* __restrict__ targets,
                     float* __restrict__ out)
{
    __shared__ int s_dxsq[SROWS][32];   // nearest dx^2 per (mask row, col); 6 KB
    __shared__ float s_warp[8];

    const int tid  = threadIdx.x;                 // 0..255
    const int lane = tid & 31;                    // column within tile
    const int w    = tid >> 5;                    // warp 0..7
    const int h0 = blockIdx.y * TILE;
    const int w0 = blockIdx.x * TILE;
    const int planeOff = blockIdx.z * (H_DIM * W_DIM);
    const int gw = w0 + lane;

    // ---- Hoist ALL global loads: one memory round, MLP ~16 ----
    // Vertical mapping: warp w owns pixel rows 4w..4w+3.
    float x0 = logits[planeOff + (h0 + 4 * w + 0) * W_DIM + gw];
    float x1 = logits[planeOff + (h0 + 4 * w + 1) * W_DIM + gw];
    float x2 = logits[planeOff + (h0 + 4 * w + 2) * W_DIM + gw];
    float x3 = logits[planeOff + (h0 + 4 * w + 3) * W_DIM + gw];

    // Horizontal mapping: warp w owns mask rows 6w..6w+5.
    const int* rowBase = targets + planeOff;
    int av[6] = {0, 0, 0, 0, 0, 0};
    int bv[6] = {0, 0, 0, 0, 0, 0};
    #pragma unroll
    for (int k = 0; k < 6; ++k) {
        int grow = h0 - HALO + 6 * w + k;          // mask row -> global row
        bool rv = (grow >= 0) && (grow < H_DIM);
        int c0 = w0 - HALO + lane;
        if (rv && c0 >= 0 && c0 < W_DIM) av[k] = __ldg(rowBase + grow * W_DIM + c0);
        int c1 = w0 + 24 + lane;
        if (rv && lane < 16 && c1 < W_DIM)  bv[k] = __ldg(rowBase + grow * W_DIM + c1);
    }

    // ---- Sigmoids early (independent of EDT; hide behind ballot phase) ----
    float p0 = __fdividef(1.0f, 1.0f + __expf(-x0));
    float p1 = __fdividef(1.0f, 1.0f + __expf(-x1));
    float p2 = __fdividef(1.0f, 1.0f + __expf(-x2));
    float p3 = __fdividef(1.0f, 1.0f + __expf(-x3));

    // ---- Ballot-assemble row masks + horizontal nearest-dx^2 pass ----
    #pragma unroll
    for (int k = 0; k < 6; ++k) {
        unsigned int lo = __ballot_sync(0xffffffffu, av[k] > 0);
        unsigned int hi = __ballot_sync(0xffffffffu, bv[k] > 0); // lanes>=16 -> 0
        // 17-bit window centered on this lane's column (bits tx..tx+16 of hi:lo)
        unsigned int win = __funnelshift_r(lo, hi, lane) & 0x1FFFFu;
        // fold: bit d of comb = seed at dx=+d (from win>>8) or dx=-d (brev fold)
        unsigned int comb = (win >> 8) | (__brev(win) >> 23);
        comb |= 0x800u;                            // sentinel dx=11 -> 121 (>81)
        int dx = __ffs(comb) - 1;
        s_dxsq[6 * w + k][lane] = dx * dx;
    }
    __syncthreads();

    // ---- Rolling vertical min-plus for 4 adjacent pixels ----
    // Pixel row py = 4w+j has mask-row center 4w+j+8; union of windows
    // covers mask rows 4w .. 4w+19.
    int vv[20];
    #pragma unroll
    for (int i = 0; i < 20; ++i) vv[i] = s_dxsq[4 * w + i][lane];

    int b[4];
    #pragma unroll
    for (int j = 0; j < 4; ++j) b[j] = vv[j + 8];
    #pragma unroll
    for (int d = 1; d <= 8; ++d) {
        #pragma unroll
        for (int j = 0; j < 4; ++j)
            b[j] = min(b[j], min(vv[j + 8 - d], vv[j + 8 + d]) + d * d);
    }
    #pragma unroll
    for (int j = 0; j < 4; ++j) {
        if (b[j] > 81)   // sentinel-contaminated or beatable from outside: exact
            b[j] = global_ring_search(targets, planeOff, h0 + 4 * w + j, gw,
                                      0x3fffffff);
    }

    float acc = fmaf(p0, __fsqrt_rn((float)b[0]), 1.0f - p0)
              + fmaf(p1, __fsqrt_rn((float)b[1]), 1.0f - p1)
              + fmaf(p2, __fsqrt_rn((float)b[2]), 1.0f - p2)
              + fmaf(p3, __fsqrt_rn((float)b[3]), 1.0f - p3);

    // ---- Deterministic block reduction (FP32, fixed order) ----
    #pragma unroll
    for (int off = 16; off > 0; off >>= 1)
        acc += __shfl_down_sync(0xffffffffu, acc, off);
    if (lane == 0) s_warp[w] = acc;
    __syncthreads();
    if (w == 0) {
        float v = (lane < 8) ? s_warp[lane] : 0.0f;
        #pragma unroll
        for (int off = 4; off > 0; off >>= 1)
            v += __shfl_down_sync(0xffffffffu, v, off);
        if (lane == 0) {
            // Q24 fixed point: integer atomics are associative -> deterministic.
            unsigned long long q = (unsigned long long)((double)v * FP_SCALE);
            atomicAdd(&g_sum, q);
            unsigned int t;
            asm volatile("atom.acq_rel.gpu.global.add.u32 %0, [%1], %2;"
                         : "=r"(t) : "l"(&g_arrived), "r"(1u) : "memory");
            if (t == (unsigned int)(NBLOCKS - 1)) {
                unsigned long long s = g_sum;
                out[0] = (float)((double)s /
                                 (FP_SCALE * (double)(B_DIM * H_DIM * W_DIM)));
                g_sum = 0ull;        // reset for next graph replay
                g_arrived = 0;
            }
        }
    }
}

extern "C" void kernel_launch(void* const* d_in, const int* in_sizes, int n_in,
                              void* d_out, int out_size)
{
    const float* logits  = (const float*)d_in[0];
    const int*   targets = (const int*)d_in[1];
    float* out = (float*)d_out;

    dim3 block(256, 1, 1);
    dim3 grid(NBLK_X, NBLK_Y, B_DIM);
    edt_loss_kernel<<<grid, block>>>(logits, targets, out);
}

// round 12
// speedup vs baseline: 1.0959x; 1.0959x over previous
#include <cuda_runtime.h>
#include <cuda_bf16.h>
#include <math.h>

// Problem constants (fixed by dataset: B=4, H=W=320)
#define H_DIM 320
#define W_DIM 320
#define B_DIM 4
#define TILE 32                 // tile is 32x32 pixels
#define BLK_Y 16                // 32x16 threads, 2 pixels per thread
#define HALO 8
#define SROWS (TILE + 2 * HALO) // 48 mask rows
#define NBLK_X (W_DIM / TILE)   // 10
#define NBLK_Y (H_DIM / TILE)   // 10
#define NBLOCKS (NBLK_X * NBLK_Y * B_DIM) // 400
#define FP_SCALE 16777216.0     // 2^24 fixed-point scale (associative int adds)

__device__ unsigned long long g_sum = 0ull;
__device__ unsigned int g_arrived = 0;

// Exact global fallback (entered with INF bound; window results <= 81 are
// provably the exact global min since outside-window seeds have d^2 >= 81).
__device__ __noinline__ int global_ring_search(const int* __restrict__ targets,
                                               int planeOff, int gh, int gw, int best)
{
    for (int r = HALO + 1; r < H_DIM + W_DIM; ++r) {
        if (r * r >= best) break;
        const int rr = r * r;
        const int yT = gh - r, yB = gh + r;
        for (int dx = -r; dx <= r; ++dx) {
            int d2 = rr + dx * dx;
            if (d2 >= best) continue;
            int x = gw + dx;
            if (x < 0 || x >= W_DIM) continue;
            if (yT >= 0 && targets[planeOff + yT * W_DIM + x] > 0) best = d2;
            if (yB < H_DIM && d2 < best && targets[planeOff + yB * W_DIM + x] > 0) best = d2;
        }
        const int xL = gw - r, xR = gw + r;
        for (int dy = -r + 1; dy <= r - 1; ++dy) {
            int d2 = rr + dy * dy;
            if (d2 >= best) continue;
            int y = gh + dy;
            if (y < 0 || y >= H_DIM) continue;
            if (xL >= 0 && targets[planeOff + y * W_DIM + xL] > 0) best = d2;
            if (xR < W_DIM && d2 < best && targets[planeOff + y * W_DIM + xR] > 0) best = d2;
        }
    }
    return best;
}

// Fused vertical min-plus for two vertically adjacent pixels (centers r, r+1).
// Rolling 2-register window: 18 LDS + ~50 ALU for BOTH pixels.
__device__ __forceinline__ void vertical_min_pair(const int* __restrict__ col,
                                                  int r, int& best0, int& best1)
{
    const int* c = col + r * 32;                // row (r+k) at c[32*k]
    int prev_up = c[0];                         // v[r - (d-1)] after step d-1
    int prev_dn = c[32];                        // v[r + d]     after step d-1
    int b0 = prev_up, b1 = prev_dn;
    #pragma unroll
    for (int d = 1; d <= 8; ++d) {
        int nu = c[-d * 32];                    // v[r - d]
        int nd = c[(d + 1) * 32];               // v[r + 1 + d]
        b0 = min(b0, min(nu, prev_dn) + d * d); // pixel0 rows r-d, r+d
        b1 = min(b1, min(prev_up, nd) + d * d); // pixel1 rows r+1-d, r+1+d
        prev_up = nu;
        prev_dn = nd;
    }
    best0 = b0;
    best1 = b1;
}

__global__ __launch_bounds__(512, 3)
void edt_loss_kernel(const float* __restrict__ logits,
                     const int* __restrict__ targets,
                     float* __restrict__ out)
{
    __shared__ int s_dxsq[SROWS][32];    // nearest dx^2 per (mask row, col); 6 KB
    __shared__ float s_warp[16];

    const int tx   = threadIdx.x;                 // 0..31 (== lane)
    const int ty   = threadIdx.y;                 // 0..15 (== warp)
    const int warp = ty;
    const int lane = tx;
    const int h0 = blockIdx.y * TILE;
    const int w0 = blockIdx.x * TILE;
    const int planeOff = blockIdx.z * (H_DIM * W_DIM);
    const int gw = w0 + tx;

    // ---- Hoist ALL global loads: one memory round, full MLP ----
    // Warp ty owns pixel rows 2ty and 2ty+1.
    float x0 = logits[planeOff + (h0 + 2 * ty) * W_DIM + gw];
    float x1 = logits[planeOff + (h0 + 2 * ty + 1) * W_DIM + gw];

    const int* rowBase = targets + planeOff;
    int av[3] = {0, 0, 0};
    int bv[3] = {0, 0, 0};
    #pragma unroll
    for (int k = 0; k < 3; ++k) {
        int grow = h0 - HALO + warp + k * 16;     // 0..47 -> global row
        bool rv = (grow >= 0) && (grow < H_DIM);
        int c0 = w0 - HALO + lane;
        if (rv && c0 >= 0 && c0 < W_DIM) av[k] = __ldg(rowBase + grow * W_DIM + c0);
        int c1 = w0 + 24 + lane;
        if (rv && lane < 16 && c1 < W_DIM)  bv[k] = __ldg(rowBase + grow * W_DIM + c1);
    }

    // ---- Sigmoids early: overlap with ballot/horizontal phase ----
    float p0 = __fdividef(1.0f, 1.0f + __expf(-x0));
    float p1 = __fdividef(1.0f, 1.0f + __expf(-x1));

    // ---- Ballot + funnelshift/brev/ffs horizontal nearest-dx^2 pass ----
    #pragma unroll
    for (int k = 0; k < 3; ++k) {
        unsigned int lo = __ballot_sync(0xffffffffu, av[k] > 0);
        unsigned int hi = __ballot_sync(0xffffffffu, bv[k] > 0); // lanes>=16 -> 0
        // 17-bit window = bits lane..lane+16 of (hi:lo)
        unsigned int win = __funnelshift_r(lo, hi, lane) & 0x1FFFFu;
        // bit d of comb = seed at dx=+d or dx=-d
        unsigned int comb = (win >> 8) | (__brev(win) >> 23);
        comb |= 0x800u;                            // sentinel dx=11 -> 121 (>81)
        int dx = __ffs(comb) - 1;
        s_dxsq[warp + k * 16][lane] = dx * dx;
    }
    __syncthreads();

    // ---- Fused vertical pass for the pixel pair + loss (FP32) ----
    const int* col = &s_dxsq[0][tx];
    int best0, best1;
    vertical_min_pair(col, 2 * ty + HALO, best0, best1);
    if (best0 > 81)   // sentinel-contaminated or beatable from outside: exact
        best0 = global_ring_search(targets, planeOff, h0 + 2 * ty, gw, 0x3fffffff);
    if (best1 > 81)
        best1 = global_ring_search(targets, planeOff, h0 + 2 * ty + 1, gw, 0x3fffffff);

    float acc = fmaf(p0, __fsqrt_rn((float)best0), 1.0f - p0)
              + fmaf(p1, __fsqrt_rn((float)best1), 1.0f - p1);

    // ---- Deterministic block reduction (FP32, fixed order) ----
    #pragma unroll
    for (int off = 16; off > 0; off >>= 1)
        acc += __shfl_down_sync(0xffffffffu, acc, off);
    if (lane == 0) s_warp[warp] = acc;
    __syncthreads();
    if (warp == 0) {
        float v = (lane < 16) ? s_warp[lane] : 0.0f;
        #pragma unroll
        for (int off = 8; off > 0; off >>= 1)
            v += __shfl_down_sync(0xffffffffu, v, off);
        if (lane == 0) {
            // Q24 fixed point: integer atomics are associative -> deterministic.
            unsigned long long q = (unsigned long long)((double)v * FP_SCALE);
            atomicAdd(&g_sum, q);
            unsigned int t;
            asm volatile("atom.acq_rel.gpu.global.add.u32 %0, [%1], %2;"
                         : "=r"(t) : "l"(&g_arrived), "r"(1u) : "memory");
            if (t == (unsigned int)(NBLOCKS - 1)) {
                unsigned long long s;
                asm volatile("ld.global.cg.u64 %0, [%1];"
                             : "=l"(s) : "l"(&g_sum) : "memory");
                out[0] = (float)((double)s /
                                 (FP_SCALE * (double)(B_DIM * H_DIM * W_DIM)));
                g_sum = 0ull;        // reset for next graph replay
                g_arrived = 0;
            }
        }
    }
}

extern "C" void kernel_launch(void* const* d_in, const int* in_sizes, int n_in,
                              void* d_out, int out_size)
{
    const float* logits  = (const float*)d_in[0];
    const int*   targets = (const int*)d_in[1];
    float* out = (float*)d_out;

    dim3 block(32, BLK_Y, 1);
    dim3 grid(NBLK_X, NBLK_Y, B_DIM);
    edt_loss_kernel<<<grid, block>>>(logits, targets, out);
}